// round 2
// baseline (speedup 1.0000x reference)
#include <cuda_runtime.h>
#include <math.h>

// ---------------------------------------------------------------------------
// Problem constants
// ---------------------------------------------------------------------------
namespace {
constexpr int B_  = 2;
constexpr int N_  = 512;
constexpr int D_  = 128;   // DIM
constexpr int PH_ = 64;    // POS_HID
constexpr int AH_ = 512;   // ATTN_HID
constexpr int K_  = 16;    // K_NEIGH
constexpr int M1  = B_ * N_;    // 1024 query rows
constexpr int M2  = M1 * K_;    // 16384 (b,i,k) rows
}

// ---------------------------------------------------------------------------
// Scratch (device globals; no runtime allocation allowed)
// ---------------------------------------------------------------------------
__device__ float g_qkv[M1 * 3 * D_];   // (b,i, [q|k|v]) rows of 384
__device__ int   g_idx[M1 * K_];       // 16 nearest neighbor indices per query
__device__ float g_H  [M2 * D_];       // qk_g + pe_g  rows
__device__ float g_VG [M2 * D_];       // v_g + pe_g   rows
__device__ float g_A  [M2 * AH_];      // relu(H@W1+b1)
__device__ float g_SIM[M2 * D_];       // A@W2+b2

// ---------------------------------------------------------------------------
// 1) qkv = x^T @ w_qkv   (one block per (b,n) row)
// ---------------------------------------------------------------------------
__global__ void qkv_kernel(const float* __restrict__ x, const float* __restrict__ w) {
    __shared__ float sx[D_];
    const int m = blockIdx.x;
    const int b = m >> 9;
    const int n = m & (N_ - 1);
    const int tid = threadIdx.x;   // 128 threads
    sx[tid] = x[b * D_ * N_ + tid * N_ + n];
    __syncthreads();
    float a0 = 0.f, a1 = 0.f, a2 = 0.f;
#pragma unroll 8
    for (int d = 0; d < D_; ++d) {
        const float xv = sx[d];
        const float* wr = w + d * (3 * D_);
        a0 = fmaf(xv, wr[tid],           a0);
        a1 = fmaf(xv, wr[tid + D_],      a1);
        a2 = fmaf(xv, wr[tid + 2 * D_],  a2);
    }
    float* o = g_qkv + m * (3 * D_);
    o[tid] = a0; o[tid + D_] = a1; o[tid + 2 * D_] = a2;
}

// ---------------------------------------------------------------------------
// 2) KNN: 16 smallest distances per query. One warp per query, 8 warps/block.
//    Ties broken toward lower index (matches jax.lax.top_k; order of the 16
//    does not matter downstream since softmax+sum over k is permutation
//    invariant).
// ---------------------------------------------------------------------------
__global__ void knn_kernel(const float* __restrict__ pos) {
    __shared__ float sx[N_], sy[N_], sz[N_];
    const int lane = threadIdx.x & 31;
    const int warp = threadIdx.x >> 5;
    const int m0 = blockIdx.x * 8;        // 8 queries per block, same b (512%8==0)
    const int b = m0 >> 9;

    for (int t = threadIdx.x; t < N_; t += blockDim.x) {
        const float* p = pos + (size_t)(b * N_ + t) * 3;
        sx[t] = p[0]; sy[t] = p[1]; sz[t] = p[2];
    }
    __syncthreads();

    const int m = m0 + warp;
    const int i = m & (N_ - 1);
    const float px = sx[i], py = sy[i], pz = sz[i];

    float d2[16];
#pragma unroll
    for (int t = 0; t < 16; ++t) {
        const int j = lane + 32 * t;
        const float dx = px - sx[j], dy = py - sy[j], dz = pz - sz[j];
        d2[t] = dx * dx + dy * dy + dz * dz;
    }

    unsigned taken = 0u;
    for (int it = 0; it < K_; ++it) {
        float best = 3.4e38f;
        int bt = -1;
#pragma unroll
        for (int t = 0; t < 16; ++t) {
            if (!((taken >> t) & 1u) && d2[t] < best) { best = d2[t]; bt = t; }
        }
        int bj = (bt < 0) ? 0x7fffffff : (lane + 32 * bt);
#pragma unroll
        for (int off = 16; off; off >>= 1) {
            const float ov = __shfl_xor_sync(0xffffffffu, best, off);
            const int   oj = __shfl_xor_sync(0xffffffffu, bj,   off);
            if (ov < best || (ov == best && oj < bj)) { best = ov; bj = oj; }
        }
        if ((bj & 31) == lane) taken |= 1u << (bj >> 5);
        if (lane == 0) g_idx[m * K_ + it] = bj;
    }
}

// ---------------------------------------------------------------------------
// 3) prep: pos-MLP (3->64->128), build H = q_i - k_j + pe and VG = v_j + pe.
//    One block (128 threads) per query; loops over its 16 neighbors.
// ---------------------------------------------------------------------------
__global__ void prep_kernel(const float* __restrict__ pos,
                            const float* __restrict__ pw1, const float* __restrict__ pb1,
                            const float* __restrict__ pw2, const float* __restrict__ pb2) {
    __shared__ float s_w2[PH_ * D_];   // 32 KB
    __shared__ float s_hid[PH_];
    __shared__ float s_q[D_];

    const int m = blockIdx.x;
    const int b = m >> 9;
    const int i = m & (N_ - 1);
    const int tid = threadIdx.x;   // 128

    for (int t = tid; t < PH_ * D_; t += blockDim.x) s_w2[t] = pw2[t];
    s_q[tid] = g_qkv[m * (3 * D_) + tid];
    const float px = pos[(size_t)(b * N_ + i) * 3 + 0];
    const float py = pos[(size_t)(b * N_ + i) * 3 + 1];
    const float pz = pos[(size_t)(b * N_ + i) * 3 + 2];
    __syncthreads();

    for (int kk = 0; kk < K_; ++kk) {
        const int j = g_idx[m * K_ + kk];
        const float rx = px - pos[(size_t)(b * N_ + j) * 3 + 0];
        const float ry = py - pos[(size_t)(b * N_ + j) * 3 + 1];
        const float rz = pz - pos[(size_t)(b * N_ + j) * 3 + 2];
        if (tid < PH_) {
            float h = pb1[tid];
            h = fmaf(rx, pw1[tid], h);
            h = fmaf(ry, pw1[PH_ + tid], h);
            h = fmaf(rz, pw1[2 * PH_ + tid], h);
            s_hid[tid] = fmaxf(h, 0.f);
        }
        __syncthreads();
        float pe = pb2[tid];
#pragma unroll 16
        for (int h = 0; h < PH_; ++h) pe = fmaf(s_hid[h], s_w2[h * D_ + tid], pe);
        const int row = m * K_ + kk;
        const float kv = g_qkv[(size_t)(b * N_ + j) * (3 * D_) + D_     + tid];
        const float vv = g_qkv[(size_t)(b * N_ + j) * (3 * D_) + 2 * D_ + tid];
        g_H [(size_t)row * D_ + tid] = s_q[tid] - kv + pe;
        g_VG[(size_t)row * D_ + tid] = vv + pe;
        __syncthreads();
    }
}

// ---------------------------------------------------------------------------
// 4/5) Tiled fp32 SGEMM: C = [relu](A @ W + bias). A:MxK, W:KxN row-major.
// ---------------------------------------------------------------------------
template <int BM, int BN, int BK, int TM, int TN, bool RELU>
__global__ void sgemm_kernel(const float* __restrict__ A, const float* __restrict__ W,
                             const float* __restrict__ bias, float* __restrict__ C,
                             int M, int N, int K) {
    constexpr int NT = (BM / TM) * (BN / TN);   // 256 threads
    __shared__ float As[BK][BM + 4];
    __shared__ float Bs[BK][BN];

    const int tid = threadIdx.x;
    const int tx = tid % (BN / TN);
    const int ty = tid / (BN / TN);
    const int m0 = blockIdx.y * BM;
    const int n0 = blockIdx.x * BN;

    float acc[TM][TN];
#pragma unroll
    for (int a = 0; a < TM; ++a)
#pragma unroll
        for (int c = 0; c < TN; ++c) acc[a][c] = 0.f;

    for (int k0 = 0; k0 < K; k0 += BK) {
#pragma unroll
        for (int t = tid; t < BM * BK / 4; t += NT) {
            const int r = t / (BK / 4), c4 = t % (BK / 4);
            const float4 v = *(const float4*)(A + (size_t)(m0 + r) * K + k0 + c4 * 4);
            As[c4 * 4 + 0][r] = v.x; As[c4 * 4 + 1][r] = v.y;
            As[c4 * 4 + 2][r] = v.z; As[c4 * 4 + 3][r] = v.w;
        }
#pragma unroll
        for (int t = tid; t < BK * BN / 4; t += NT) {
            const int r = t / (BN / 4), c4 = t % (BN / 4);
            *(float4*)(&Bs[r][c4 * 4]) = *(const float4*)(W + (size_t)(k0 + r) * N + n0 + c4 * 4);
        }
        __syncthreads();
#pragma unroll
        for (int kk = 0; kk < BK; ++kk) {
            float ra[TM], rb[TN];
#pragma unroll
            for (int a = 0; a < TM; ++a) ra[a] = As[kk][ty * TM + a];
#pragma unroll
            for (int c = 0; c < TN; ++c) rb[c] = Bs[kk][tx * TN + c];
#pragma unroll
            for (int a = 0; a < TM; ++a)
#pragma unroll
                for (int c = 0; c < TN; ++c) acc[a][c] = fmaf(ra[a], rb[c], acc[a][c]);
        }
        __syncthreads();
    }

#pragma unroll
    for (int a = 0; a < TM; ++a) {
        const int mr = m0 + ty * TM + a;
#pragma unroll
        for (int c = 0; c < TN; ++c) {
            const int nc = n0 + tx * TN + c;
            float v = acc[a][c] + bias[nc];
            if (RELU) v = fmaxf(v, 0.f);
            C[(size_t)mr * N + nc] = v;
        }
    }
}

// ---------------------------------------------------------------------------
// 6) softmax over k (per channel d) + weighted sum, write transposed output.
// ---------------------------------------------------------------------------
__global__ void finalize_kernel(float* __restrict__ out) {
    __shared__ float ss[K_][D_ + 1];
    __shared__ float sv[K_][D_ + 1];
    const int m = blockIdx.x;
    const int b = m >> 9;
    const int i = m & (N_ - 1);
    const int tid = threadIdx.x;   // 128

    for (int t = tid; t < K_ * D_; t += blockDim.x) {
        const int kk = t >> 7, d = t & (D_ - 1);
        ss[kk][d] = g_SIM[(size_t)(m * K_ + kk) * D_ + d];
        sv[kk][d] = g_VG [(size_t)(m * K_ + kk) * D_ + d];
    }
    __syncthreads();

    const int d = tid;
    float mx = -3.4e38f;
#pragma unroll
    for (int kk = 0; kk < K_; ++kk) mx = fmaxf(mx, ss[kk][d]);
    float s = 0.f, agg = 0.f;
#pragma unroll
    for (int kk = 0; kk < K_; ++kk) {
        const float e = expf(ss[kk][d] - mx);
        s += e;
        agg = fmaf(e, sv[kk][d], agg);
    }
    out[(size_t)b * D_ * N_ + (size_t)d * N_ + i] = agg / s;
}

// ---------------------------------------------------------------------------
// Launch
// ---------------------------------------------------------------------------
extern "C" void kernel_launch(void* const* d_in, const int* in_sizes, int n_in,
                              void* d_out, int out_size) {
    const float* x    = (const float*)d_in[0];
    const float* pos  = (const float*)d_in[1];
    const float* wqkv = (const float*)d_in[2];
    const float* pw1  = (const float*)d_in[3];
    const float* pb1  = (const float*)d_in[4];
    const float* pw2  = (const float*)d_in[5];
    const float* pb2  = (const float*)d_in[6];
    const float* aw1  = (const float*)d_in[7];
    const float* ab1  = (const float*)d_in[8];
    const float* aw2  = (const float*)d_in[9];
    const float* ab2  = (const float*)d_in[10];
    float* out = (float*)d_out;

    void *pH = nullptr, *pA = nullptr, *pS = nullptr;
    cudaGetSymbolAddress(&pH, g_H);
    cudaGetSymbolAddress(&pA, g_A);
    cudaGetSymbolAddress(&pS, g_SIM);

    qkv_kernel<<<M1, 128>>>(x, wqkv);
    knn_kernel<<<M1 / 8, 256>>>(pos);
    prep_kernel<<<M1, 128>>>(pos, pw1, pb1, pw2, pb2);
    sgemm_kernel<128, 128, 16, 8, 8, true ><<<dim3(AH_ / 128, M2 / 128), 256>>>(
        (const float*)pH, aw1, ab1, (float*)pA, M2, AH_, D_);
    sgemm_kernel<128,  64, 16, 8, 4, false><<<dim3(D_ /  64, M2 / 128), 256>>>(
        (const float*)pA, aw2, ab2, (float*)pS, M2, D_, AH_);
    finalize_kernel<<<M1, 128>>>(out);
}

// round 3
// speedup vs baseline: 1.9346x; 1.9346x over previous
#include <cuda_runtime.h>
#include <math.h>
#include <stdint.h>

// ---------------------------------------------------------------------------
// Problem constants
// ---------------------------------------------------------------------------
namespace {
constexpr int B_  = 2;
constexpr int N_  = 512;
constexpr int D_  = 128;   // DIM
constexpr int PH_ = 64;    // POS_HID
constexpr int AH_ = 512;   // ATTN_HID
constexpr int K_  = 16;    // K_NEIGH
constexpr int M1  = B_ * N_;    // 1024 query rows
constexpr int M2  = M1 * K_;    // 16384 (b,i,k) rows
}

// ---------------------------------------------------------------------------
// Scratch (device globals; no runtime allocation allowed)
// ---------------------------------------------------------------------------
__device__ float g_qkv[M1 * 3 * D_];   // (b,i, [q|k|v]) rows of 384
__device__ int   g_idx[M1 * K_];       // 16 nearest neighbor indices per query
__device__ float g_H  [M2 * D_];       // qk_g + pe_g  rows
__device__ float g_VG [M2 * D_];       // v_g + pe_g   rows
__device__ float g_A  [M2 * AH_];      // relu(H@W1+b1)
__device__ float g_SIM[M2 * D_];       // A@W2+b2

// ---------------------------------------------------------------------------
// 1) qkv = x^T @ w_qkv   (one block per (b,n) row)
// ---------------------------------------------------------------------------
__global__ void qkv_kernel(const float* __restrict__ x, const float* __restrict__ w) {
    __shared__ float sx[D_];
    const int m = blockIdx.x;
    const int b = m >> 9;
    const int n = m & (N_ - 1);
    const int tid = threadIdx.x;   // 128 threads
    sx[tid] = x[b * D_ * N_ + tid * N_ + n];
    __syncthreads();
    float a0 = 0.f, a1 = 0.f, a2 = 0.f;
#pragma unroll 8
    for (int d = 0; d < D_; ++d) {
        const float xv = sx[d];
        const float* wr = w + d * (3 * D_);
        a0 = fmaf(xv, wr[tid],           a0);
        a1 = fmaf(xv, wr[tid + D_],      a1);
        a2 = fmaf(xv, wr[tid + 2 * D_],  a2);
    }
    float* o = g_qkv + m * (3 * D_);
    o[tid] = a0; o[tid + D_] = a1; o[tid + 2 * D_] = a2;
}

// ---------------------------------------------------------------------------
// 2) KNN: 16 smallest distances per query. One warp per query, 8 warps/block.
// ---------------------------------------------------------------------------
__global__ void knn_kernel(const float* __restrict__ pos) {
    __shared__ float sx[N_], sy[N_], sz[N_];
    const int lane = threadIdx.x & 31;
    const int warp = threadIdx.x >> 5;
    const int m0 = blockIdx.x * 8;        // 8 queries per block, same b
    const int b = m0 >> 9;

    for (int t = threadIdx.x; t < N_; t += blockDim.x) {
        const float* p = pos + (size_t)(b * N_ + t) * 3;
        sx[t] = p[0]; sy[t] = p[1]; sz[t] = p[2];
    }
    __syncthreads();

    const int m = m0 + warp;
    const int i = m & (N_ - 1);
    const float px = sx[i], py = sy[i], pz = sz[i];

    float d2[16];
#pragma unroll
    for (int t = 0; t < 16; ++t) {
        const int j = lane + 32 * t;
        const float dx = px - sx[j], dy = py - sy[j], dz = pz - sz[j];
        d2[t] = dx * dx + dy * dy + dz * dz;
    }

    unsigned taken = 0u;
    for (int it = 0; it < K_; ++it) {
        float best = 3.4e38f;
        int bt = -1;
#pragma unroll
        for (int t = 0; t < 16; ++t) {
            if (!((taken >> t) & 1u) && d2[t] < best) { best = d2[t]; bt = t; }
        }
        int bj = (bt < 0) ? 0x7fffffff : (lane + 32 * bt);
#pragma unroll
        for (int off = 16; off; off >>= 1) {
            const float ov = __shfl_xor_sync(0xffffffffu, best, off);
            const int   oj = __shfl_xor_sync(0xffffffffu, bj,   off);
            if (ov < best || (ov == best && oj < bj)) { best = ov; bj = oj; }
        }
        if ((bj & 31) == lane) taken |= 1u << (bj >> 5);
        if (lane == 0) g_idx[m * K_ + it] = bj;
    }
}

// ---------------------------------------------------------------------------
// 3) prep: pos-MLP (3->64->128), build H = q_i - k_j + pe and VG = v_j + pe.
// ---------------------------------------------------------------------------
__global__ void prep_kernel(const float* __restrict__ pos,
                            const float* __restrict__ pw1, const float* __restrict__ pb1,
                            const float* __restrict__ pw2, const float* __restrict__ pb2) {
    __shared__ float s_w2[PH_ * D_];   // 32 KB
    __shared__ float s_hid[PH_];
    __shared__ float s_q[D_];

    const int m = blockIdx.x;
    const int b = m >> 9;
    const int i = m & (N_ - 1);
    const int tid = threadIdx.x;   // 128

    for (int t = tid; t < PH_ * D_; t += blockDim.x) s_w2[t] = pw2[t];
    s_q[tid] = g_qkv[m * (3 * D_) + tid];
    const float px = pos[(size_t)(b * N_ + i) * 3 + 0];
    const float py = pos[(size_t)(b * N_ + i) * 3 + 1];
    const float pz = pos[(size_t)(b * N_ + i) * 3 + 2];
    __syncthreads();

    for (int kk = 0; kk < K_; ++kk) {
        const int j = g_idx[m * K_ + kk];
        const float rx = px - pos[(size_t)(b * N_ + j) * 3 + 0];
        const float ry = py - pos[(size_t)(b * N_ + j) * 3 + 1];
        const float rz = pz - pos[(size_t)(b * N_ + j) * 3 + 2];
        if (tid < PH_) {
            float h = pb1[tid];
            h = fmaf(rx, pw1[tid], h);
            h = fmaf(ry, pw1[PH_ + tid], h);
            h = fmaf(rz, pw1[2 * PH_ + tid], h);
            s_hid[tid] = fmaxf(h, 0.f);
        }
        __syncthreads();
        float pe = pb2[tid];
#pragma unroll 16
        for (int h = 0; h < PH_; ++h) pe = fmaf(s_hid[h], s_w2[h * D_ + tid], pe);
        const int row = m * K_ + kk;
        const float kv = g_qkv[(size_t)(b * N_ + j) * (3 * D_) + D_     + tid];
        const float vv = g_qkv[(size_t)(b * N_ + j) * (3 * D_) + 2 * D_ + tid];
        g_H [(size_t)row * D_ + tid] = s_q[tid] - kv + pe;
        g_VG[(size_t)row * D_ + tid] = vv + pe;
        __syncthreads();
    }
}

// ---------------------------------------------------------------------------
// 4/5) Tensor-core tf32 GEMM: C = [relu](A @ W + bias).
//   A: MxK row-major, W: KxN row-major.  BM=BN=128, BK=32.
//   8 warps (2x4), warp tile 64x32, mma.sync.m16n8k8.tf32.
//   fp32->tf32 conversion happens once on the global->smem path.
// ---------------------------------------------------------------------------
__device__ __forceinline__ uint32_t f2tf32(float f) {
    uint32_t u;
    asm("cvt.rna.tf32.f32 %0, %1;" : "=r"(u) : "f"(f));
    return u;
}

__device__ __forceinline__ void mma_tf32(float c[4],
                                         uint32_t a0, uint32_t a1, uint32_t a2, uint32_t a3,
                                         uint32_t b0, uint32_t b1) {
    asm volatile(
        "mma.sync.aligned.m16n8k8.row.col.f32.tf32.tf32.f32 "
        "{%0,%1,%2,%3}, {%4,%5,%6,%7}, {%8,%9}, {%0,%1,%2,%3};"
        : "+f"(c[0]), "+f"(c[1]), "+f"(c[2]), "+f"(c[3])
        : "r"(a0), "r"(a1), "r"(a2), "r"(a3), "r"(b0), "r"(b1));
}

template <bool RELU>
__global__ __launch_bounds__(256)
void tc_gemm(const float* __restrict__ A, const float* __restrict__ W,
             const float* __restrict__ bias, float* __restrict__ C,
             int M, int N, int K) {
    // Padded so fragment LDS is conflict-free:
    //  A-frag bank = (36*r + c) % 32 = (4r + c): r=lane>>2 in 0..7, c=lane&3 -> unique.
    //  B-frag bank = (136*k + n) % 32 = (8k + n): k=lane&3 in 0..3, n=lane>>2 in 0..7 -> unique.
    __shared__ uint32_t As[128][36];
    __shared__ uint32_t Bs[32][136];

    const int tid  = threadIdx.x;
    const int lane = tid & 31;
    const int warp = tid >> 5;
    const int wm = (warp >> 2) * 64;   // warp row offset inside tile
    const int wn = (warp & 3) * 32;    // warp col offset inside tile
    const int m0 = blockIdx.y * 128;
    const int n0 = blockIdx.x * 128;

    float acc[4][4][4];
#pragma unroll
    for (int mi = 0; mi < 4; ++mi)
#pragma unroll
        for (int ni = 0; ni < 4; ++ni)
#pragma unroll
            for (int e = 0; e < 4; ++e) acc[mi][ni][e] = 0.f;

    for (int k0 = 0; k0 < K; k0 += 32) {
        // ---- stage A tile (128x32) ----
#pragma unroll
        for (int t = 0; t < 4; ++t) {
            const int idx = tid + t * 256;
            const int r = idx >> 3, c = (idx & 7) << 2;
            const float4 v = *(const float4*)(A + (size_t)(m0 + r) * K + k0 + c);
            As[r][c + 0] = f2tf32(v.x); As[r][c + 1] = f2tf32(v.y);
            As[r][c + 2] = f2tf32(v.z); As[r][c + 3] = f2tf32(v.w);
        }
        // ---- stage B tile (32x128) ----
#pragma unroll
        for (int t = 0; t < 4; ++t) {
            const int idx = tid + t * 256;
            const int kr = idx >> 5, nc = (idx & 31) << 2;
            const float4 v = *(const float4*)(W + (size_t)(k0 + kr) * N + n0 + nc);
            Bs[kr][nc + 0] = f2tf32(v.x); Bs[kr][nc + 1] = f2tf32(v.y);
            Bs[kr][nc + 2] = f2tf32(v.z); Bs[kr][nc + 3] = f2tf32(v.w);
        }
        __syncthreads();

#pragma unroll
        for (int ks = 0; ks < 4; ++ks) {
            const int kk = ks * 8;
            uint32_t af[4][4], bf[4][2];
#pragma unroll
            for (int mi = 0; mi < 4; ++mi) {
                const int rb = wm + mi * 16 + (lane >> 2);
                const int cb = kk + (lane & 3);
                af[mi][0] = As[rb    ][cb    ];
                af[mi][1] = As[rb + 8][cb    ];
                af[mi][2] = As[rb    ][cb + 4];
                af[mi][3] = As[rb + 8][cb + 4];
            }
#pragma unroll
            for (int ni = 0; ni < 4; ++ni) {
                const int nb = wn + ni * 8 + (lane >> 2);
                bf[ni][0] = Bs[kk +     (lane & 3)][nb];
                bf[ni][1] = Bs[kk + 4 + (lane & 3)][nb];
            }
#pragma unroll
            for (int mi = 0; mi < 4; ++mi)
#pragma unroll
                for (int ni = 0; ni < 4; ++ni)
                    mma_tf32(acc[mi][ni], af[mi][0], af[mi][1], af[mi][2], af[mi][3],
                             bf[ni][0], bf[ni][1]);
        }
        __syncthreads();
    }

    // ---- epilogue: bias (+relu), direct global stores ----
#pragma unroll
    for (int mi = 0; mi < 4; ++mi) {
#pragma unroll
        for (int ni = 0; ni < 4; ++ni) {
            const int r0 = m0 + wm + mi * 16 + (lane >> 2);
            const int c0 = n0 + wn + ni * 8 + ((lane & 3) << 1);
            const float bv0 = bias[c0], bv1 = bias[c0 + 1];
            float v0 = acc[mi][ni][0] + bv0;
            float v1 = acc[mi][ni][1] + bv1;
            float v2 = acc[mi][ni][2] + bv0;
            float v3 = acc[mi][ni][3] + bv1;
            if (RELU) {
                v0 = fmaxf(v0, 0.f); v1 = fmaxf(v1, 0.f);
                v2 = fmaxf(v2, 0.f); v3 = fmaxf(v3, 0.f);
            }
            *(float2*)(C + (size_t)r0 * N + c0)       = make_float2(v0, v1);
            *(float2*)(C + (size_t)(r0 + 8) * N + c0) = make_float2(v2, v3);
        }
    }
}

// ---------------------------------------------------------------------------
// 6) softmax over k (per channel d) + weighted sum, write transposed output.
// ---------------------------------------------------------------------------
__global__ void finalize_kernel(float* __restrict__ out) {
    __shared__ float ss[K_][D_ + 1];
    __shared__ float sv[K_][D_ + 1];
    const int m = blockIdx.x;
    const int b = m >> 9;
    const int i = m & (N_ - 1);
    const int tid = threadIdx.x;   // 128

    for (int t = tid; t < K_ * D_; t += blockDim.x) {
        const int kk = t >> 7, d = t & (D_ - 1);
        ss[kk][d] = g_SIM[(size_t)(m * K_ + kk) * D_ + d];
        sv[kk][d] = g_VG [(size_t)(m * K_ + kk) * D_ + d];
    }
    __syncthreads();

    const int d = tid;
    float mx = -3.4e38f;
#pragma unroll
    for (int kk = 0; kk < K_; ++kk) mx = fmaxf(mx, ss[kk][d]);
    float s = 0.f, agg = 0.f;
#pragma unroll
    for (int kk = 0; kk < K_; ++kk) {
        const float e = expf(ss[kk][d] - mx);
        s += e;
        agg = fmaf(e, sv[kk][d], agg);
    }
    out[(size_t)b * D_ * N_ + (size_t)d * N_ + i] = agg / s;
}

// ---------------------------------------------------------------------------
// Launch
// ---------------------------------------------------------------------------
extern "C" void kernel_launch(void* const* d_in, const int* in_sizes, int n_in,
                              void* d_out, int out_size) {
    const float* x    = (const float*)d_in[0];
    const float* pos  = (const float*)d_in[1];
    const float* wqkv = (const float*)d_in[2];
    const float* pw1  = (const float*)d_in[3];
    const float* pb1  = (const float*)d_in[4];
    const float* pw2  = (const float*)d_in[5];
    const float* pb2  = (const float*)d_in[6];
    const float* aw1  = (const float*)d_in[7];
    const float* ab1  = (const float*)d_in[8];
    const float* aw2  = (const float*)d_in[9];
    const float* ab2  = (const float*)d_in[10];
    float* out = (float*)d_out;

    void *pH = nullptr, *pA = nullptr, *pS = nullptr;
    cudaGetSymbolAddress(&pH, g_H);
    cudaGetSymbolAddress(&pA, g_A);
    cudaGetSymbolAddress(&pS, g_SIM);

    qkv_kernel<<<M1, 128>>>(x, wqkv);
    knn_kernel<<<M1 / 8, 256>>>(pos);
    prep_kernel<<<M1, 128>>>(pos, pw1, pb1, pw2, pb2);
    tc_gemm<true ><<<dim3(AH_ / 128, M2 / 128), 256>>>(
        (const float*)pH, aw1, ab1, (float*)pA, M2, AH_, D_);
    tc_gemm<false><<<dim3(D_ / 128, M2 / 128), 256>>>(
        (const float*)pA, aw2, ab2, (float*)pS, M2, D_, AH_);
    finalize_kernel<<<M1, 128>>>(out);
}